// round 16
// baseline (speedup 1.0000x reference)
#include <cuda_runtime.h>
#include <cstdint>

// Embedding gather, fully fused, bin overlapped UNDER the W stream:
//   x : [16384] int32 token ids        (d_in[0])
//   W : [1024, 50257] f32 row-major    (d_in[1]); embedding of tok = column tok
//   out[s, :] = W[:, x[s]]
//
// Single kernel, grid (786, 16). Blocks (y==0, x<64) bin the 16384 tokens
// by tok>>6 (786 windows of 64 ids = 256B) — they are linear bids 0..63,
// guaranteed wave-1 resident. The LOAD phase (stream the 256B window for a
// 64-dim chunk into smem, evict-first) depends only on W, so EVERY block
// runs it immediately; the g_binDone wait sits between load and store,
// where binning (~2us) has already been hidden under the first wave's load
// (~4us). Store phase: warp-per-token conflict-free LDS + coalesced 128B
// write-through rows. Counters self-reset via R12's proven chain.

#define TOKENS    50257
#define DIMS      1024
#define NTOK      16384
#define BSHIFT    6
#define WIN       64
#define NBUCKETS  ((TOKENS + WIN - 1) / WIN)   // 786
#define CAP       160
#define DIM_CHUNK 64
#define NCHUNKS   (DIMS / DIM_CHUNK)           // 16
#define TPAD      65                           // odd: conflict-free LDS stride
#define NBIN      64                           // binning blocks

__device__ int  g_cnt[NBUCKETS];               // zero at load; self-reset
__device__ int  g_done[NBUCKETS];              // per-bucket arrivals; self-reset
__device__ int  g_allDone;                     // buckets completed; self-reset
__device__ volatile int g_binDone;             // bin blocks finished; self-reset
__device__ int2 g_items[NBUCKETS * CAP];       // (tok, original position)

__global__ __launch_bounds__(256, 8)
void k_fused(const int* __restrict__ x,
             const float* __restrict__ W,
             float* __restrict__ out)
{
    __shared__ float tile[DIM_CHUNK * TPAD];   // [dim][token col]
    __shared__ int s_tok[CAP], s_pos[CAP];
    __shared__ int s_n;

    const int b    = blockIdx.x;
    const int tid  = threadIdx.x;
    const int lane = tid & 31;
    const int wid  = tid >> 5;

    // ---- Bin phase: blocks (y==0, x<64) only; 64*256 = 16384 tokens. ----
    if (blockIdx.y == 0 && b < NBIN) {
        int i   = b * 256 + tid;
        int tok = __ldg(&x[i]);
        int bb  = tok >> BSHIFT;
        int s   = atomicAdd(&g_cnt[bb], 1);
        if (s < CAP) g_items[bb * CAP + s] = make_int2(tok, i);
        __threadfence();                       // publish items/counts
        __syncthreads();
        if (tid == 0) atomicAdd((int*)&g_binDone, 1);
    }

    // ---- Load phase: bin-independent — starts immediately on all blocks.
    const int w    = b << BSHIFT;
    const int dim0 = blockIdx.y * DIM_CHUNK;
    const int c    = tid & 63;                 // lane-consecutive -> 128B LDG
    const int d0   = tid >> 6;                 // 0..3

    const float* p  = W + (size_t)(dim0 + d0) * TOKENS + w + c;
    float*       tp = tile + d0 * TPAD + c;

    if (b != NBUCKETS - 1) {                   // full 64-token window
#pragma unroll
        for (int i = 0; i < 16; i++)
            tp[i * (4 * TPAD)] = __ldcs(p + (size_t)i * (4 * TOKENS));
    } else {                                   // last window: 17 valid cols
        const bool ok = (c < TOKENS - w);
#pragma unroll
        for (int i = 0; i < 16; i++)
            tp[i * (4 * TPAD)] = ok ? __ldcs(p + (size_t)i * (4 * TOKENS)) : 0.0f;
    }

    // ---- Wait for binning (usually already complete). ----
    if (tid == 0) {
        while (g_binDone < NBIN) __nanosleep(32);
        s_n = min(g_cnt[b], CAP);
    }
    __syncthreads();
    __threadfence();                           // acquire: order item reads
    const int n = s_n;

    if (n > 0) {
        if (tid < n) {                         // n <= CAP(160) < 256
            int2 e = g_items[b * CAP + tid];
            s_tok[tid] = e.x;
            s_pos[tid] = e.y;
        }
        __syncthreads();                       // s_tok/s_pos + tile ready

        // ---- Store phase: warp per token; 2 coalesced 128B WT rows. ----
        for (int t = wid; t < n; t += 8) {
            const int tcol = s_tok[t] - w;
            float* orow = out + (size_t)s_pos[t] * DIMS + dim0;
            __stwt(&orow[lane],      tile[lane * TPAD + tcol]);
            __stwt(&orow[32 + lane], tile[(32 + lane) * TPAD + tcol]);
        }
    }

    // ---- Self-reset chain (g_binDone cleared only after ALL buckets
    //      complete — every block has passed the spin by then). ----
    __syncthreads();
    if (tid == 0) {
        if (atomicAdd(&g_done[b], 1) == NCHUNKS - 1) {
            g_cnt[b]  = 0;
            g_done[b] = 0;
            if (atomicAdd(&g_allDone, 1) == NBUCKETS - 1) {
                g_allDone = 0;
                g_binDone = 0;
            }
        }
    }
}

extern "C" void kernel_launch(void* const* d_in, const int* in_sizes, int n_in,
                              void* d_out, int out_size)
{
    const int*   x = (const int*)  d_in[0];
    const float* W = (const float*)d_in[1];
    float*       o = (float*)      d_out;

    dim3 grid(NBUCKETS, NCHUNKS);              // (786, 16)
    k_fused<<<grid, 256>>>(x, W, o);
}

// round 17
// speedup vs baseline: 1.0267x; 1.0267x over previous
#include <cuda_runtime.h>
#include <cstdint>

// Embedding gather: W streamed via cp.async.bulk (TMA bulk copy) + PDL:
//   x : [16384] int32 token ids        (d_in[0])
//   W : [1024, 50257] f32 row-major    (d_in[1]); embedding of tok = column tok
//   out[s, :] = W[:, x[s]]
//
// k_bin    : bucket tokens by tok>>6 (786 windows of 64 ids = 256B); PDL.
// k_gather : block = (bucket, 64-dim chunk). Load phase: 64 cp.async.bulk
//            copies (one 272B row each, floored to 16B alignment) issued by
//            lanes 0..63 — replaces 4096 LDG+STS with 64 UBLKCP, freeing
//            issue slots and L1 wavefronts so DRAM can run at its ceiling.
//            Completion via mbarrier expect_tx. Store phase: warp-per-token
//            LDS (4-way conflict, small volume) + coalesced 128B WT rows.

#define TOKENS    50257
#define DIMS      1024
#define NTOK      16384
#define BSHIFT    6
#define WIN       64
#define NBUCKETS  ((TOKENS + WIN - 1) / WIN)   // 786
#define CAP       160
#define DIM_CHUNK 64
#define NCHUNKS   (DIMS / DIM_CHUNK)           // 16
#define RSTRIDE   68                           // smem row stride (floats) = 272B
#define ROW_BYTES 272
#define TILE_BYTES (DIM_CHUNK * ROW_BYTES)     // 17408

// tile index: row d shifted by its 16B-floor phase (d%4 floats)
#define TIDX(d, c) ((d) * RSTRIDE + ((d) & 3) + (c))

__device__ int  g_cnt[NBUCKETS];               // zero at load; self-reset
__device__ int  g_done[NBUCKETS];              // arrival counters; self-reset
__device__ int2 g_items[NBUCKETS * CAP];       // (tok, original position)

__global__ void k_bin(const int* __restrict__ x)
{
    int i = blockIdx.x * blockDim.x + threadIdx.x;
    if (i < NTOK) {
        int tok = __ldg(&x[i]);
        int b   = tok >> BSHIFT;
        int s   = atomicAdd(&g_cnt[b], 1);
        if (s < CAP) g_items[b * CAP + s] = make_int2(tok, i);
    }
    cudaTriggerProgrammaticLaunchCompletion();
}

// grid (786, 16), 256 threads = 8 warps.
__global__ __launch_bounds__(256, 8)
void k_gather(const float* __restrict__ W, float* __restrict__ out)
{
    __shared__ __align__(16) float tile[DIM_CHUNK * RSTRIDE];
    __shared__ __align__(8) unsigned long long mbar;
    __shared__ int s_tok[CAP], s_pos[CAP];
    __shared__ int s_n;

    const int b    = blockIdx.x;
    const int tid  = threadIdx.x;
    const int lane = tid & 31;
    const int wid  = tid >> 5;

    cudaGridDependencySynchronize();           // k_bin results visible

    const uint32_t mbar_a = (uint32_t)__cvta_generic_to_shared(&mbar);
    const uint32_t tile_a = (uint32_t)__cvta_generic_to_shared(tile);
    const int w    = b << BSHIFT;
    const int dim0 = blockIdx.y * DIM_CHUNK;
    const bool last = (b == NBUCKETS - 1);

    if (tid == 0) {
        asm volatile("mbarrier.init.shared.b64 [%0], 1;" :: "r"(mbar_a) : "memory");
        s_n = min(g_cnt[b], CAP);
    }
    __syncthreads();
    const int n = s_n;

    // ---- Load phase ----
    if (!last) {
        if (tid == 0) {
            asm volatile("mbarrier.arrive.expect_tx.shared.b64 _, [%0], %1;"
                         :: "r"(mbar_a), "r"(DIM_CHUNK * ROW_BYTES) : "memory");
        }
        if (tid < DIM_CHUNK) {                  // lane d copies dim-row d
            const float* src = W + (size_t)(dim0 + tid) * TOKENS + w;
            const void* src16 = (const void*)((uintptr_t)src & ~(uintptr_t)15);
            asm volatile(
                "cp.async.bulk.shared::cta.global.mbarrier::complete_tx::bytes "
                "[%0], [%1], %2, [%3];"
                :: "r"(tile_a + tid * ROW_BYTES), "l"(src16),
                   "r"(ROW_BYTES), "r"(mbar_a) : "memory");
        }
    } else {                                    // last window: 17 valid cols
        const int c  = tid & 63;
        const int d0 = tid >> 6;
        const bool ok = (c < TOKENS - w);
#pragma unroll
        for (int i = 0; i < 16; i++) {
            int d = d0 + 4 * i;
            tile[TIDX(d, c)] =
                ok ? __ldcs(W + (size_t)(dim0 + d) * TOKENS + w + c) : 0.0f;
        }
    }

    // Prefetch bucket entries while copies are in flight.
    if (tid < n) {                              // n <= CAP(160) < 256
        int2 e = g_items[b * CAP + tid];
        s_tok[tid] = e.x;
        s_pos[tid] = e.y;
    }

    // ---- Wait for bulk copies ----
    if (!last) {
        asm volatile(
            "{\n\t.reg .pred P;\n"
            "WAIT_%=:\n\t"
            "mbarrier.try_wait.parity.acquire.cta.shared::cta.b64 P, [%0], 0, 0x989680;\n\t"
            "@P bra.uni DONE_%=;\n\t"
            "bra.uni WAIT_%=;\n"
            "DONE_%=:\n\t}"
            :: "r"(mbar_a) : "memory");
    }
    __syncthreads();                            // tile + s_tok/s_pos ready

    // ---- Store phase: warp per token; 2 coalesced 128B WT rows. ----
    for (int t = wid; t < n; t += 8) {
        const int tcol = s_tok[t] - w;
        float* orow = out + (size_t)s_pos[t] * DIMS + dim0;
        __stwt(&orow[lane],      tile[TIDX(lane, tcol)]);
        __stwt(&orow[32 + lane], tile[TIDX(32 + lane, tcol)]);
    }

    // Self-reset: last chunk-block per bucket restores counters.
    __syncthreads();
    if (tid == 0) {
        if (atomicAdd(&g_done[b], 1) == NCHUNKS - 1) {
            g_cnt[b]  = 0;
            g_done[b] = 0;
        }
    }
}

extern "C" void kernel_launch(void* const* d_in, const int* in_sizes, int n_in,
                              void* d_out, int out_size)
{
    const int*   x = (const int*)  d_in[0];
    const float* W = (const float*)d_in[1];
    float*       o = (float*)      d_out;

    k_bin<<<(NTOK + 255) / 256, 256>>>(x);

    cudaLaunchConfig_t cfg = {};
    cfg.gridDim  = dim3(NBUCKETS, NCHUNKS);    // (786, 16)
    cfg.blockDim = dim3(256);
    cfg.stream   = 0;
    cudaLaunchAttribute attr[1];
    attr[0].id = cudaLaunchAttributeProgrammaticStreamSerialization;
    attr[0].val.programmaticStreamSerializationAllowed = 1;
    cfg.attrs    = attr;
    cfg.numAttrs = 1;
    cudaLaunchKernelEx(&cfg, k_gather, W, o);
}